// round 5
// baseline (speedup 1.0000x reference)
#include <cuda_runtime.h>

// Problem constants (fixed by the dataset)
#define T_LEN 4096
#define B_SZ  32
#define C_SZ  300
#define W_SZ  128
#define C4    (C_SZ / 4)     // 75 float4 per (t,b) row
#define ROW4  (B_SZ * C4)    // 2400 float4 per t-slice
#define NTHR  480            // 2400 = 480 * 5 exactly
#define UNROLL 5
#define T_PER 2              // t-slices per block (prologue amortization)

// Fused kernel: one block per 2 consecutive t.
// The duration scan (starts/total) is t-independent, so it runs ONCE per
// block; only the cheap ballot/select runs per t. Streaming regs are reused
// across the two slices, so register pressure stays at the R3 level.
__global__ void __launch_bounds__(NTHR) k_fused(const float4* __restrict__ x,
                                                const float4* __restrict__ pe,
                                                const int*    __restrict__ dur,
                                                float4*       __restrict__ out) {
    __shared__ int s_pos[T_PER][B_SZ];
    const int t0   = blockIdx.x * T_PER;
    const int warp = threadIdx.x >> 5;
    const int lane = threadIdx.x & 31;
    const int tid  = threadIdx.x;

    // ---- prologue: scan once, select per t ----
    if (warp < 8) {
#pragma unroll
        for (int k = 0; k < 4; k++) {
            const int b = warp * 4 + k;
            int4 d4 = *(const int4*)(dur + b * W_SZ + lane * 4);
            int s = d4.x + d4.y + d4.z + d4.w;
            int incl = s;
#pragma unroll
            for (int o = 1; o < 32; o <<= 1) {
                int vv = __shfl_up_sync(0xffffffffu, incl, o);
                if (lane >= o) incl += vv;
            }
            int base = incl - s;                   // exclusive prefix across lanes
            int st0 = base;
            int st1 = base + d4.x;
            int st2 = st1 + d4.y;
            int st3 = st2 + d4.z;
            int tot = __shfl_sync(0xffffffffu, incl, 31);

#pragma unroll
            for (int tt = 0; tt < T_PER; tt++) {
                const int t = t0 + tt;
                // Largest start <= t: starts nondecreasing across lanes.
                unsigned m = __ballot_sync(0xffffffffu, st0 <= t);
                int L = 31 - __clz(m);
                int loc = st0;
                if (st1 <= t) loc = st1;
                if (st2 <= t) loc = st2;
                if (st3 <= t) loc = st3;
                int seg = __shfl_sync(0xffffffffu, loc, L);
                if (lane == 0) s_pos[tt][b] = (t < tot) ? (t - seg) : -1;
            }
        }
    }
    __syncthreads();

    // ---- index math shared by both slices ----
    int bb[UNROLL], cc[UNROLL];
#pragma unroll
    for (int i = 0; i < UNROLL; i++) {
        int j = tid + i * NTHR;
        bb[i] = j / C4;                    // constant divide -> mul/shift
        cc[i] = j - bb[i] * C4;
    }

    // ---- stream both slices ----
#pragma unroll
    for (int tt = 0; tt < T_PER; tt++) {
        const float4* xrow = x + (size_t)(t0 + tt) * ROW4;
        float4*       orow = out + (size_t)(t0 + tt) * ROW4;

        float4 v[UNROLL];
#pragma unroll
        for (int i = 0; i < UNROLL; i++)
            v[i] = __ldcs(xrow + tid + i * NTHR);   // streaming read
#pragma unroll
        for (int i = 0; i < UNROLL; i++) {
            int p = s_pos[tt][bb[i]];
            if (p >= 0) {
                float4 pv = __ldg(pe + p * C4 + cc[i]);   // L2-resident table
                v[i].x += pv.x; v[i].y += pv.y; v[i].z += pv.z; v[i].w += pv.w;
            }
        }
#pragma unroll
        for (int i = 0; i < UNROLL; i++)
            __stcs(orow + tid + i * NTHR, v[i]);    // streaming write
    }
}

extern "C" void kernel_launch(void* const* d_in, const int* in_sizes, int n_in,
                              void* d_out, int out_size) {
    const float* x  = (const float*)d_in[0];
    const float* pe = (const float*)d_in[1];
    const int*   du = (const int*)d_in[2];
    // d_in[3] = train flag, unused by the reference math.
    k_fused<<<T_LEN / T_PER, NTHR>>>((const float4*)x, (const float4*)pe, du,
                                     (float4*)d_out);
}